// round 6
// baseline (speedup 1.0000x reference)
#include <cuda_runtime.h>
#include <cuda_bf16.h>

// ProjectBEV: input (B=16, H=64, W=2048, CK=3, 2) float32.
// Flattened element order is (B, CK, H, W)  [reference transposes (0,3,1,2,4)].
// N = B*CK*H*W = 6,291,456.
// Output (float32, concatenated):
//   [0      , 6N )  presence_indices rows [b, qx, qy, c, h, w]
//   [6N     , 7N )  presence_vals (all 1)
//   [7N     , 21N)  position_indices rows [b, qx, qy, c, h, w, d] for d=0,1
//   [21N    , 23N)  position_vals [sx, sy] per element
// sx = 2x+1, sy = 2y+81, qx = trunc(sx), qy = trunc(sy).

#define W_DIM 2048
#define H_DIM 64
#define CK_DIM 3

__global__ __launch_bounds__(256)
void project_bev_kernel(const float* __restrict__ in,
                        float* __restrict__ out,
                        long N)
{
    const long nPairs = N >> 1;
    const long t = (long)blockIdx.x * blockDim.x + threadIdx.x;
    if (t >= nPairs) return;

    const long i0 = t << 1;

    float sxv[2], syv[2];      // scaled coords
    float qx[2], qy[2];        // truncated (as float)
    float bf[2], cf[2], hf[2], wf[2];

#pragma unroll
    for (int e = 0; e < 2; e++) {
        const long idx = i0 + e;
        const int w  = (int)(idx & (long)(W_DIM - 1));
        const int h  = (int)((idx >> 11) & (long)(H_DIM - 1));
        const int hi = (int)(idx >> 17);          // = b*CK + c, max 47
        const int b  = hi / CK_DIM;
        const int c  = hi - CK_DIM * b;

        // input linear offset in float2 units: (((b*H + h)*W + w)*CK + c)
        const int in_off = ((b * H_DIM + h) * W_DIM + w) * CK_DIM + c;
        const float2 xy = __ldcs(((const float2*)in) + in_off);

        const float sx = xy.x * 2.0f + 1.0f;   // 2x exact -> rounding identical to XLA
        const float sy = xy.y * 2.0f + 81.0f;
        sxv[e] = sx; syv[e] = sy;
        qx[e] = (float)(int)sx;                // positive -> trunc == astype(int64)
        qy[e] = (float)(int)sy;
        bf[e] = (float)b; cf[e] = (float)c;
        hf[e] = (float)h; wf[e] = (float)w;
    }

    // ---- presence_indices: 12 floats at out[12*t] (48B stride, 16B-aligned) ----
    {
        float4* p = (float4*)(out + 12 * t);
        __stcs(p + 0, make_float4(bf[0], qx[0], qy[0], cf[0]));
        __stcs(p + 1, make_float4(hf[0], wf[0], bf[1], qx[1]));
        __stcs(p + 2, make_float4(qy[1], cf[1], hf[1], wf[1]));
    }

    // ---- presence_vals: 2 floats at out[6N + 2t], 8B-aligned ----
    __stcs((float2*)(out + 6 * N + 2 * t), make_float2(1.0f, 1.0f));

    // ---- position_indices: 28 floats at out[7N + 28t] (112B stride, 16B-aligned) ----
    {
        float r[28];
        int k = 0;
#pragma unroll
        for (int e = 0; e < 2; e++) {
#pragma unroll
            for (int d = 0; d < 2; d++) {
                r[k++] = bf[e]; r[k++] = qx[e]; r[k++] = qy[e];
                r[k++] = cf[e]; r[k++] = hf[e]; r[k++] = wf[e];
                r[k++] = (float)d;
            }
        }
        float4* p = (float4*)(out + 7 * N + 28 * t);
#pragma unroll
        for (int j = 0; j < 7; j++)
            __stcs(p + j, make_float4(r[4*j], r[4*j+1], r[4*j+2], r[4*j+3]));
    }

    // ---- position_vals: 4 floats at out[21N + 4t], 16B-aligned ----
    __stcs((float4*)(out + 21 * N + 4 * t),
           make_float4(sxv[0], syv[0], sxv[1], syv[1]));
}

extern "C" void kernel_launch(void* const* d_in, const int* in_sizes, int n_in,
                              void* d_out, int out_size)
{
    const float* in = (const float*)d_in[0];
    float* out = (float*)d_out;

    // in_sizes[0] = B*H*W*CK*2 ; N = number of (x,y) points
    const long N = (long)in_sizes[0] / 2;
    const long nPairs = N / 2;

    const int threads = 256;
    const int blocks = (int)((nPairs + threads - 1) / threads);
    project_bev_kernel<<<blocks, threads>>>(in, out, N);
}